// round 3
// baseline (speedup 1.0000x reference)
#include <cuda_runtime.h>
#include <cstdint>
#include <math.h>

#define S_LEN 2048
#define HID   1024
#define NH    16
#define HD    64
#define BATCH 2
#define ROWS  (BATCH * S_LEN)   // 4096

// -------- scratch (static __device__ arrays; no allocation allowed) --------
__device__ float g_qkv[(size_t)ROWS * 3 * HID];  // [4096][3072]
__device__ float g_att[(size_t)ROWS * HID];      // [4096][1024]
__device__ float g_cos[S_LEN * 32];
__device__ float g_sin[S_LEN * 32];

// ===================== 3xtf32 split + mma.sync helpers =====================
__device__ __forceinline__ void split32(float f, uint32_t& hi, uint32_t& lo) {
    asm("cvt.rna.tf32.f32 %0, %1;" : "=r"(hi) : "f"(f));
    float r = f - __uint_as_float(hi);
    asm("cvt.rna.tf32.f32 %0, %1;" : "=r"(lo) : "f"(r));
}

__device__ __forceinline__ void mma8(float* c,
    uint32_t a0, uint32_t a1, uint32_t a2, uint32_t a3, uint32_t b0, uint32_t b1)
{
    asm volatile(
        "mma.sync.aligned.m16n8k8.row.col.f32.tf32.tf32.f32 "
        "{%0,%1,%2,%3}, {%4,%5,%6,%7}, {%8,%9}, {%0,%1,%2,%3};"
        : "+f"(c[0]), "+f"(c[1]), "+f"(c[2]), "+f"(c[3])
        : "r"(a0), "r"(a1), "r"(a2), "r"(a3), "r"(b0), "r"(b1));
}

// ======================= tensor-core 3xtf32 GEMM ===========================
// C[M,N] = A[M,K]*B[K,N], row-major. 128x128 CTA tile, BK=16, double-buffered.
// smem stage layout (floats): Ah[2560] Al[2560] Bh[2560] Bl[2560] (row stride 20)
// k stored permuted: perm(k) = (k&3)*4 + (k>>2)  -> thread's 4 k's contiguous.
#define TSTR 20
#define STAGE_F 10240
#define GEMM_SMEM (2 * STAGE_F * 4)   // 81920 B

__device__ __forceinline__ void load_tile(
    const float* __restrict__ A, const float* __restrict__ B,
    int K, int N, int m0, int n0, int k0, float* stage, int tid)
{
    uint32_t* Ah = (uint32_t*)stage;
    uint32_t* Al = Ah + 2560;
    uint32_t* Bh = Ah + 5120;
    uint32_t* Bl = Ah + 7680;

    // A: 128 rows x 16 k ; thread: row=tid>>1, k-half=(tid&1)*8
    {
        const int ar = tid >> 1, kb = (tid & 1) << 3;
        const float* Ap = A + (size_t)(m0 + ar) * K + k0 + kb;
#pragma unroll
        for (int q = 0; q < 2; q++) {
            float4 v = *(const float4*)(Ap + 4 * q);
            float vv[4] = {v.x, v.y, v.z, v.w};
#pragma unroll
            for (int e = 0; e < 4; e++) {
                int k = kb + 4 * q + e;
                int p = ((k & 3) << 2) | (k >> 2);
                uint32_t h, l; split32(vv[e], h, l);
                Ah[ar * TSTR + p] = h;
                Al[ar * TSTR + p] = l;
            }
        }
    }
    // B: 16 k-rows x 128 n ; thread: k=tid>>4, n-base=(tid&15)*8
    {
        const int kr = tid >> 4, nb = (tid & 15) << 3;
        const int p = ((kr & 3) << 2) | (kr >> 2);
        const float* Bp = B + (size_t)(k0 + kr) * N + n0 + nb;
#pragma unroll
        for (int q = 0; q < 2; q++) {
            float4 v = *(const float4*)(Bp + 4 * q);
            float vv[4] = {v.x, v.y, v.z, v.w};
#pragma unroll
            for (int e = 0; e < 4; e++) {
                int n = nb + 4 * q + e;
                uint32_t h, l; split32(vv[e], h, l);
                Bh[n * TSTR + p] = h;
                Bl[n * TSTR + p] = l;
            }
        }
    }
}

__device__ __forceinline__ void compute_tile(
    const float* stage, float c[2][8][4], int wm0, int wn0, int g, int tig)
{
    const uint32_t* Ah = (const uint32_t*)stage;
    const uint32_t* Al = Ah + 2560;
    const uint32_t* Bh = Ah + 5120;
    const uint32_t* Bl = Ah + 7680;

    uint4 bh[8], bl[8];
#pragma unroll
    for (int j = 0; j < 8; j++) {
        int n = wn0 + 8 * j + g;
        bh[j] = *(const uint4*)(Bh + n * TSTR + 4 * tig);
        bl[j] = *(const uint4*)(Bl + n * TSTR + 4 * tig);
    }
#pragma unroll
    for (int i = 0; i < 2; i++) {
        int r0 = wm0 + 16 * i + g;
        uint4 ah0 = *(const uint4*)(Ah + r0 * TSTR + 4 * tig);
        uint4 ah1 = *(const uint4*)(Ah + (r0 + 8) * TSTR + 4 * tig);
        uint4 al0 = *(const uint4*)(Al + r0 * TSTR + 4 * tig);
        uint4 al1 = *(const uint4*)(Al + (r0 + 8) * TSTR + 4 * tig);
#pragma unroll
        for (int j = 0; j < 8; j++) {
            // k-step 0 (k = tig, tig+4): hi*hi, hi*lo, lo*hi
            mma8(c[i][j], ah0.x, ah1.x, ah0.y, ah1.y, bh[j].x, bh[j].y);
            mma8(c[i][j], ah0.x, ah1.x, ah0.y, ah1.y, bl[j].x, bl[j].y);
            mma8(c[i][j], al0.x, al1.x, al0.y, al1.y, bh[j].x, bh[j].y);
            // k-step 1 (k = tig+8, tig+12)
            mma8(c[i][j], ah0.z, ah1.z, ah0.w, ah1.w, bh[j].z, bh[j].w);
            mma8(c[i][j], ah0.z, ah1.z, ah0.w, ah1.w, bl[j].z, bl[j].w);
            mma8(c[i][j], al0.z, al1.z, al0.w, al1.w, bh[j].z, bh[j].w);
        }
    }
}

__global__ __launch_bounds__(256) void gemm_mma(
    const float* __restrict__ A, const float* __restrict__ B,
    float* __restrict__ C, int M, int N, int K)
{
    extern __shared__ float sm[];
    const int tid = threadIdx.x;
    const int wid = tid >> 5, lane = tid & 31;
    const int g = lane >> 2, tig = lane & 3;
    const int m0 = blockIdx.y * 128, n0 = blockIdx.x * 128;
    const int wm0 = (wid & 3) * 32, wn0 = (wid >> 2) * 64;

    float c[2][8][4];
#pragma unroll
    for (int i = 0; i < 2; i++)
#pragma unroll
        for (int j = 0; j < 8; j++)
#pragma unroll
            for (int q = 0; q < 4; q++) c[i][j][q] = 0.f;

    const int T = K >> 4;
    load_tile(A, B, K, N, m0, n0, 0, sm, tid);
    __syncthreads();
    for (int t = 0; t < T; t++) {
        if (t + 1 < T)
            load_tile(A, B, K, N, m0, n0, (t + 1) << 4, sm + ((t + 1) & 1) * STAGE_F, tid);
        compute_tile(sm + (t & 1) * STAGE_F, c, wm0, wn0, g, tig);
        __syncthreads();
    }

#pragma unroll
    for (int i = 0; i < 2; i++) {
        int row = m0 + wm0 + 16 * i + g;
#pragma unroll
        for (int j = 0; j < 8; j++) {
            int col = n0 + wn0 + 8 * j + 2 * tig;
            *(float2*)(C + (size_t)row * N + col)       = make_float2(c[i][j][0], c[i][j][1]);
            *(float2*)(C + (size_t)(row + 8) * N + col) = make_float2(c[i][j][2], c[i][j][3]);
        }
    }
}

// ============================ RoPE tables ==================================
__global__ void rope_tables_kernel()
{
    int idx = blockIdx.x * blockDim.x + threadIdx.x;
    if (idx >= S_LEN * 32) return;
    int s = idx >> 5, j = idx & 31;
    double inv = exp(-((double)j / 32.0) * log(160000.0));
    double ang = (double)s * inv;
    g_cos[idx] = (float)cos(ang);
    g_sin[idx] = (float)sin(ang);
}

// ======================= RoPE apply (in-place on qkv) ======================
__global__ __launch_bounds__(256) void rope_apply_kernel()
{
    int idx = blockIdx.x * blockDim.x + threadIdx.x;
    if (idx >= ROWS * 1024) return;
    int row  = idx >> 10;
    int rem  = idx & 1023;
    int t    = rem >> 9;
    int rem2 = rem & 511;
    int h    = rem2 >> 5;
    int j    = rem2 & 31;
    int s    = row & (S_LEN - 1);

    size_t base = (size_t)row * 3072 + (size_t)t * HID + h * HD;
    float x1 = g_qkv[base + j];
    float x2 = g_qkv[base + j + 32];
    float c  = g_cos[s * 32 + j];
    float sn = g_sin[s * 32 + j];
    g_qkv[base + j]      = x1 * c - x2 * sn;
    g_qkv[base + j + 32] = x2 * c + x1 * sn;
}

// ======================= fused causal flash attention ======================
__global__ __launch_bounds__(256) void attn_kernel(
    const float* __restrict__ qkv, float* __restrict__ out)
{
    extern __shared__ float sm[];
    float* Qs   = sm;            // 64*65
    float* Ks   = sm + 4160;
    float* Vs   = sm + 8320;
    float* Ss   = sm + 12480;
    float* m_sh = sm + 16640;
    float* l_sh = sm + 16704;

    const int tid = threadIdx.x;
    const int qt = blockIdx.x, bh = blockIdx.y;
    const int b = bh >> 4, h = bh & 15;
    const int q0 = qt * 64;
    const size_t rowbase = (size_t)b * S_LEN;
    const int qoff = h * HD, koff = HID + h * HD, voff = 2 * HID + h * HD;

    const int i = tid >> 2, g = tid & 3;

    for (int f = tid; f < 1024; f += 256) {
        int r = f >> 4, c4 = (f & 15) << 2;
        float4 v = *(const float4*)(qkv + (rowbase + q0 + r) * 3072 + qoff + c4);
        Qs[r * 65 + c4 + 0] = v.x; Qs[r * 65 + c4 + 1] = v.y;
        Qs[r * 65 + c4 + 2] = v.z; Qs[r * 65 + c4 + 3] = v.w;
    }
    if (tid < 64) { m_sh[tid] = -INFINITY; l_sh[tid] = 0.f; }

    float O[16];
#pragma unroll
    for (int c = 0; c < 16; c++) O[c] = 0.f;

    for (int j0 = 0; j0 <= q0; j0 += 64) {
        __syncthreads();
        for (int f = tid; f < 1024; f += 256) {
            int r = f >> 4, c4 = (f & 15) << 2;
            const float* rowp = qkv + (rowbase + j0 + r) * 3072;
            float4 kv = *(const float4*)(rowp + koff + c4);
            Ks[r * 65 + c4 + 0] = kv.x; Ks[r * 65 + c4 + 1] = kv.y;
            Ks[r * 65 + c4 + 2] = kv.z; Ks[r * 65 + c4 + 3] = kv.w;
            float4 vv = *(const float4*)(rowp + voff + c4);
            Vs[r * 65 + c4 + 0] = vv.x; Vs[r * 65 + c4 + 1] = vv.y;
            Vs[r * 65 + c4 + 2] = vv.z; Vs[r * 65 + c4 + 3] = vv.w;
        }
        float m_prev = m_sh[i];
        __syncthreads();

        float s[16];
#pragma unroll
        for (int jj = 0; jj < 16; jj++) s[jj] = 0.f;
        for (int d = 0; d < 64; d++) {
            float qv = Qs[i * 65 + d];
#pragma unroll
            for (int jj = 0; jj < 16; jj++)
                s[jj] += qv * Ks[(g + (jj << 2)) * 65 + d];
        }

        const bool diag = (j0 == q0);
        float mloc = -INFINITY;
#pragma unroll
        for (int jj = 0; jj < 16; jj++) {
            float val = s[jj] * 0.125f;
            if (diag && (g + (jj << 2)) > i) val = -1e9f;
            s[jj] = val;
            mloc = fmaxf(mloc, val);
        }
        mloc = fmaxf(mloc, __shfl_xor_sync(0xffffffffu, mloc, 1));
        mloc = fmaxf(mloc, __shfl_xor_sync(0xffffffffu, mloc, 2));
        float m_new = fmaxf(m_prev, mloc);

        float ssum = 0.f;
#pragma unroll
        for (int jj = 0; jj < 16; jj++) {
            float p = expf(s[jj] - m_new);
            ssum += p;
            Ss[i * 65 + g + (jj << 2)] = p;
        }
        ssum += __shfl_xor_sync(0xffffffffu, ssum, 1);
        ssum += __shfl_xor_sync(0xffffffffu, ssum, 2);
        float alpha = expf(m_prev - m_new);
        if (g == 0) { m_sh[i] = m_new; l_sh[i] = l_sh[i] * alpha + ssum; }
        __syncthreads();

#pragma unroll
        for (int c = 0; c < 16; c++) O[c] *= alpha;
        for (int j = 0; j < 64; j++) {
            float pv = Ss[i * 65 + j];
#pragma unroll
            for (int c = 0; c < 16; c++)
                O[c] += pv * Vs[j * 65 + g + (c << 2)];
        }
    }

    __syncthreads();
    float linv = 1.0f / l_sh[i];
#pragma unroll
    for (int c = 0; c < 16; c++)
        out[(rowbase + q0 + i) * HID + h * HD + g + (c << 2)] = O[c] * linv;
}

// ================================ launch ===================================
extern "C" void kernel_launch(void* const* d_in, const int* in_sizes, int n_in,
                              void* d_out, int out_size)
{
    const float* hidden = (const float*)d_in[0];
    const float* Wqkv = (const float*)d_in[2];
    const float* Wo   = (const float*)d_in[3];
    float* out = (float*)d_out;

    float *qkv_ptr, *att_ptr;
    cudaGetSymbolAddress((void**)&qkv_ptr, g_qkv);
    cudaGetSymbolAddress((void**)&att_ptr, g_att);

    rope_tables_kernel<<<(S_LEN * 32 + 255) / 256, 256>>>();

    cudaFuncSetAttribute(gemm_mma, cudaFuncAttributeMaxDynamicSharedMemorySize, GEMM_SMEM);
    gemm_mma<<<dim3(3 * HID / 128, ROWS / 128), 256, GEMM_SMEM>>>(hidden, Wqkv, qkv_ptr, ROWS, 3 * HID, HID);

    rope_apply_kernel<<<(ROWS * 1024) / 256, 256>>>();

    const int SMEM = 16768 * 4;
    cudaFuncSetAttribute(attn_kernel, cudaFuncAttributeMaxDynamicSharedMemorySize, SMEM);
    dim3 g2(S_LEN / 64, BATCH * NH);
    attn_kernel<<<g2, 256, SMEM>>>(qkv_ptr, att_ptr);

    gemm_mma<<<dim3(HID / 128, ROWS / 128), 256, GEMM_SMEM>>>(att_ptr, Wo, out, ROWS, HID, HID);
}

// round 4
// speedup vs baseline: 1.2040x; 1.2040x over previous
#include <cuda_runtime.h>
#include <cstdint>
#include <math.h>

#define S_LEN 2048
#define HID   1024
#define NH    16
#define HD    64
#define BATCH 2
#define ROWS  (BATCH * S_LEN)   // 4096

// -------- scratch (static __device__ arrays; no allocation allowed) --------
__device__ float g_qkv[(size_t)ROWS * 3 * HID];  // [4096][3072]
__device__ float g_att[(size_t)ROWS * HID];      // [4096][1024]
__device__ float g_cos[S_LEN * 32];
__device__ float g_sin[S_LEN * 32];

// ===================== 3xtf32 split + mma.sync helpers =====================
__device__ __forceinline__ void split32(float f, uint32_t& hi, uint32_t& lo) {
    asm("cvt.rna.tf32.f32 %0, %1;" : "=r"(hi) : "f"(f));
    float r = f - __uint_as_float(hi);
    asm("cvt.rna.tf32.f32 %0, %1;" : "=r"(lo) : "f"(r));
}

__device__ __forceinline__ void mma8(float* c,
    uint32_t a0, uint32_t a1, uint32_t a2, uint32_t a3, uint32_t b0, uint32_t b1)
{
    asm volatile(
        "mma.sync.aligned.m16n8k8.row.col.f32.tf32.tf32.f32 "
        "{%0,%1,%2,%3}, {%4,%5,%6,%7}, {%8,%9}, {%0,%1,%2,%3};"
        : "+f"(c[0]), "+f"(c[1]), "+f"(c[2]), "+f"(c[3])
        : "r"(a0), "r"(a1), "r"(a2), "r"(a3), "r"(b0), "r"(b1));
}

// ======================= tensor-core 3xtf32 GEMM ===========================
// C[M,N] = A[M,K]*B[K,N], row-major. 128x128 CTA tile, BK=16.
// smem: per row of 16 k's, 4 uint4 groups; group g holds k = {g,g+4,g+8,g+12};
// stored at uint4-index  row*4 + (g ^ ((row>>1)&3))  -> conflict-free STS & LDS.
// Pipeline: regs=LDG(t) prefetched; sync; STS(t); sync; LDG(t+1); compute(t).

#define FRAG(arr, r) ((arr)[(r) * 4 + (tig ^ (((r) >> 1) & 3))])

__global__ __launch_bounds__(256, 2) void gemm_mma(
    const float* __restrict__ A, const float* __restrict__ B,
    float* __restrict__ C, int M, int N, int K)
{
    __shared__ uint4 smq[2048];            // 32 KB: Ah[512] Al[512] Bh[512] Bl[512]
    uint4* Ah = smq;
    uint4* Al = smq + 512;
    uint4* Bh = smq + 1024;
    uint4* Bl = smq + 1536;

    const int tid = threadIdx.x;
    const int wid = tid >> 5, lane = tid & 31;
    const int gl = lane >> 2, tig = lane & 3;
    const int m0 = blockIdx.y * 128, n0 = blockIdx.x * 128;
    const int wm0 = (wid & 3) * 32, wn0 = (wid >> 2) * 64;

    const bool isA = tid < 128;
    const int rowi = isA ? tid : (tid - 128);
    const float* gp = isA ? (A + (size_t)(m0 + rowi) * K) : (B + n0 + rowi);
    uint4* Hi = isA ? Ah : Bh;
    uint4* Lo = isA ? Al : Bl;
    const int swz = (rowi >> 1) & 3;

    float c[2][8][4];
#pragma unroll
    for (int i = 0; i < 2; i++)
#pragma unroll
        for (int j = 0; j < 8; j++)
#pragma unroll
            for (int q = 0; q < 4; q++) c[i][j][q] = 0.f;

    float st[16];
    const int T = K >> 4;

    // prefetch tile 0
    if (isA) {
#pragma unroll
        for (int q = 0; q < 4; q++) {
            float4 v = *(const float4*)(gp + 4 * q);
            st[4 * q] = v.x; st[4 * q + 1] = v.y; st[4 * q + 2] = v.z; st[4 * q + 3] = v.w;
        }
    } else {
#pragma unroll
        for (int k = 0; k < 16; k++) st[k] = gp[(size_t)k * N];
    }

    for (int t = 0; t < T; t++) {
        __syncthreads();                  // compute(t-1) done reading smem
        // split + store tile t
#pragma unroll
        for (int g = 0; g < 4; g++) {
            uint32_t h0, h1, h2, h3, l0, l1, l2, l3;
            split32(st[g],      h0, l0);
            split32(st[g + 4],  h1, l1);
            split32(st[g + 8],  h2, l2);
            split32(st[g + 12], h3, l3);
            Hi[rowi * 4 + (g ^ swz)] = make_uint4(h0, h1, h2, h3);
            Lo[rowi * 4 + (g ^ swz)] = make_uint4(l0, l1, l2, l3);
        }
        __syncthreads();                  // smem tile t ready

        // prefetch tile t+1 into regs (consumed after next sync -> hidden)
        if (t + 1 < T) {
            const int k0 = (t + 1) << 4;
            if (isA) {
#pragma unroll
                for (int q = 0; q < 4; q++) {
                    float4 v = *(const float4*)(gp + k0 + 4 * q);
                    st[4 * q] = v.x; st[4 * q + 1] = v.y; st[4 * q + 2] = v.z; st[4 * q + 3] = v.w;
                }
            } else {
                const float* bp = gp + (size_t)k0 * N;
#pragma unroll
                for (int k = 0; k < 16; k++) st[k] = bp[(size_t)k * N];
            }
        }

        // compute tile t
        uint4 bh[8];
#pragma unroll
        for (int j = 0; j < 8; j++) bh[j] = FRAG(Bh, wn0 + 8 * j + gl);
#pragma unroll
        for (int i = 0; i < 2; i++) {
            const int r0 = wm0 + 16 * i + gl;
            uint4 ah0 = FRAG(Ah, r0);
            uint4 ah1 = FRAG(Ah, r0 + 8);
            uint4 al0 = FRAG(Al, r0);
            uint4 al1 = FRAG(Al, r0 + 8);
#pragma unroll
            for (int j = 0; j < 8; j++) {
                uint4 blj = FRAG(Bl, wn0 + 8 * j + gl);
                // k-step 0 (k = tig, tig+4)
                mma8(c[i][j], ah0.x, ah1.x, ah0.y, ah1.y, bh[j].x, bh[j].y);
                mma8(c[i][j], ah0.x, ah1.x, ah0.y, ah1.y, blj.x, blj.y);
                mma8(c[i][j], al0.x, al1.x, al0.y, al1.y, bh[j].x, bh[j].y);
                // k-step 1 (k = tig+8, tig+12)
                mma8(c[i][j], ah0.z, ah1.z, ah0.w, ah1.w, bh[j].z, bh[j].w);
                mma8(c[i][j], ah0.z, ah1.z, ah0.w, ah1.w, blj.z, blj.w);
                mma8(c[i][j], al0.z, al1.z, al0.w, al1.w, bh[j].z, bh[j].w);
            }
        }
    }

#pragma unroll
    for (int i = 0; i < 2; i++) {
        int row = m0 + wm0 + 16 * i + gl;
#pragma unroll
        for (int j = 0; j < 8; j++) {
            int col = n0 + wn0 + 8 * j + 2 * tig;
            *(float2*)(C + (size_t)row * N + col)       = make_float2(c[i][j][0], c[i][j][1]);
            *(float2*)(C + (size_t)(row + 8) * N + col) = make_float2(c[i][j][2], c[i][j][3]);
        }
    }
}

// ============================ RoPE tables ==================================
__global__ void rope_tables_kernel()
{
    int idx = blockIdx.x * blockDim.x + threadIdx.x;
    if (idx >= S_LEN * 32) return;
    int s = idx >> 5, j = idx & 31;
    double inv = exp(-((double)j / 32.0) * log(160000.0));
    double ang = (double)s * inv;
    g_cos[idx] = (float)cos(ang);
    g_sin[idx] = (float)sin(ang);
}

// ======================= RoPE apply (in-place on qkv) ======================
__global__ __launch_bounds__(256) void rope_apply_kernel()
{
    int idx = blockIdx.x * blockDim.x + threadIdx.x;
    if (idx >= ROWS * 1024) return;
    int row  = idx >> 10;
    int rem  = idx & 1023;
    int t    = rem >> 9;
    int rem2 = rem & 511;
    int h    = rem2 >> 5;
    int j    = rem2 & 31;
    int s    = row & (S_LEN - 1);

    size_t base = (size_t)row * 3072 + (size_t)t * HID + h * HD;
    float x1 = g_qkv[base + j];
    float x2 = g_qkv[base + j + 32];
    float c  = g_cos[s * 32 + j];
    float sn = g_sin[s * 32 + j];
    g_qkv[base + j]      = x1 * c - x2 * sn;
    g_qkv[base + j + 32] = x2 * c + x1 * sn;
}

// ======================= fused causal flash attention ======================
__global__ __launch_bounds__(256) void attn_kernel(
    const float* __restrict__ qkv, float* __restrict__ out)
{
    extern __shared__ float sm[];
    float* Qs   = sm;            // 64*65
    float* Ks   = sm + 4160;
    float* Vs   = sm + 8320;
    float* Ss   = sm + 12480;
    float* m_sh = sm + 16640;
    float* l_sh = sm + 16704;

    const int tid = threadIdx.x;
    const int qt = blockIdx.x, bh = blockIdx.y;
    const int b = bh >> 4, h = bh & 15;
    const int q0 = qt * 64;
    const size_t rowbase = (size_t)b * S_LEN;
    const int qoff = h * HD, koff = HID + h * HD, voff = 2 * HID + h * HD;

    const int i = tid >> 2, g = tid & 3;

    for (int f = tid; f < 1024; f += 256) {
        int r = f >> 4, c4 = (f & 15) << 2;
        float4 v = *(const float4*)(qkv + (rowbase + q0 + r) * 3072 + qoff + c4);
        Qs[r * 65 + c4 + 0] = v.x; Qs[r * 65 + c4 + 1] = v.y;
        Qs[r * 65 + c4 + 2] = v.z; Qs[r * 65 + c4 + 3] = v.w;
    }
    if (tid < 64) { m_sh[tid] = -INFINITY; l_sh[tid] = 0.f; }

    float O[16];
#pragma unroll
    for (int c = 0; c < 16; c++) O[c] = 0.f;

    for (int j0 = 0; j0 <= q0; j0 += 64) {
        __syncthreads();
        for (int f = tid; f < 1024; f += 256) {
            int r = f >> 4, c4 = (f & 15) << 2;
            const float* rowp = qkv + (rowbase + j0 + r) * 3072;
            float4 kv = *(const float4*)(rowp + koff + c4);
            Ks[r * 65 + c4 + 0] = kv.x; Ks[r * 65 + c4 + 1] = kv.y;
            Ks[r * 65 + c4 + 2] = kv.z; Ks[r * 65 + c4 + 3] = kv.w;
            float4 vv = *(const float4*)(rowp + voff + c4);
            Vs[r * 65 + c4 + 0] = vv.x; Vs[r * 65 + c4 + 1] = vv.y;
            Vs[r * 65 + c4 + 2] = vv.z; Vs[r * 65 + c4 + 3] = vv.w;
        }
        float m_prev = m_sh[i];
        __syncthreads();

        float s[16];
#pragma unroll
        for (int jj = 0; jj < 16; jj++) s[jj] = 0.f;
        for (int d = 0; d < 64; d++) {
            float qv = Qs[i * 65 + d];
#pragma unroll
            for (int jj = 0; jj < 16; jj++)
                s[jj] += qv * Ks[(g + (jj << 2)) * 65 + d];
        }

        const bool diag = (j0 == q0);
        float mloc = -INFINITY;
#pragma unroll
        for (int jj = 0; jj < 16; jj++) {
            float val = s[jj] * 0.125f;
            if (diag && (g + (jj << 2)) > i) val = -1e9f;
            s[jj] = val;
            mloc = fmaxf(mloc, val);
        }
        mloc = fmaxf(mloc, __shfl_xor_sync(0xffffffffu, mloc, 1));
        mloc = fmaxf(mloc, __shfl_xor_sync(0xffffffffu, mloc, 2));
        float m_new = fmaxf(m_prev, mloc);

        float ssum = 0.f;
#pragma unroll
        for (int jj = 0; jj < 16; jj++) {
            float p = expf(s[jj] - m_new);
            ssum += p;
            Ss[i * 65 + g + (jj << 2)] = p;
        }
        ssum += __shfl_xor_sync(0xffffffffu, ssum, 1);
        ssum += __shfl_xor_sync(0xffffffffu, ssum, 2);
        float alpha = expf(m_prev - m_new);
        if (g == 0) { m_sh[i] = m_new; l_sh[i] = l_sh[i] * alpha + ssum; }
        __syncthreads();

#pragma unroll
        for (int c = 0; c < 16; c++) O[c] *= alpha;
        for (int j = 0; j < 64; j++) {
            float pv = Ss[i * 65 + j];
#pragma unroll
            for (int c = 0; c < 16; c++)
                O[c] += pv * Vs[j * 65 + g + (c << 2)];
        }
    }

    __syncthreads();
    float linv = 1.0f / l_sh[i];
#pragma unroll
    for (int c = 0; c < 16; c++)
        out[(rowbase + q0 + i) * HID + h * HD + g + (c << 2)] = O[c] * linv;
}

// ================================ launch ===================================
extern "C" void kernel_launch(void* const* d_in, const int* in_sizes, int n_in,
                              void* d_out, int out_size)
{
    const float* hidden = (const float*)d_in[0];
    const float* Wqkv = (const float*)d_in[2];
    const float* Wo   = (const float*)d_in[3];
    float* out = (float*)d_out;

    float *qkv_ptr, *att_ptr;
    cudaGetSymbolAddress((void**)&qkv_ptr, g_qkv);
    cudaGetSymbolAddress((void**)&att_ptr, g_att);

    rope_tables_kernel<<<(S_LEN * 32 + 255) / 256, 256>>>();

    gemm_mma<<<dim3(3 * HID / 128, ROWS / 128), 256>>>(hidden, Wqkv, qkv_ptr, ROWS, 3 * HID, HID);

    rope_apply_kernel<<<(ROWS * 1024) / 256, 256>>>();

    const int SMEM = 16768 * 4;
    cudaFuncSetAttribute(attn_kernel, cudaFuncAttributeMaxDynamicSharedMemorySize, SMEM);
    dim3 g2(S_LEN / 64, BATCH * NH);
    attn_kernel<<<g2, 256, SMEM>>>(qkv_ptr, att_ptr);

    gemm_mma<<<dim3(HID / 128, ROWS / 128), 256>>>(att_ptr, Wo, out, ROWS, HID, HID);
}

// round 6
// speedup vs baseline: 1.9269x; 1.6004x over previous
#include <cuda_runtime.h>
#include <cstdint>
#include <math.h>

#define S_LEN 2048
#define HID   1024
#define NH    16
#define HD    64
#define BATCH 2
#define ROWS  (BATCH * S_LEN)   // 4096

typedef unsigned long long u64;

// -------- scratch (static __device__ arrays; no allocation allowed) --------
__device__ float g_qkv[(size_t)ROWS * 3 * HID];  // [4096][3072]
__device__ float g_att[(size_t)ROWS * HID];      // [4096][1024]
__device__ float g_cos[S_LEN * 32];
__device__ float g_sin[S_LEN * 32];

// ======================= packed f32x2 helpers ==============================
__device__ __forceinline__ u64 pack2(float x, float y) {
    u64 r; asm("mov.b64 %0, {%1,%2};" : "=l"(r) : "f"(x), "f"(y)); return r;
}
__device__ __forceinline__ void fma2(u64& d, u64 a, u64 b) {
    asm("fma.rn.f32x2 %0, %1, %2, %0;" : "+l"(d) : "l"(a), "l"(b));
}
__device__ __forceinline__ u64 mul2(u64 a, u64 b) {
    u64 r; asm("mul.rn.f32x2 %0, %1, %2;" : "=l"(r) : "l"(a), "l"(b)); return r;
}
__device__ __forceinline__ float2 unpack2(u64 v) {
    float2 r; asm("mov.b64 {%0,%1}, %2;" : "=f"(r.x), "=f"(r.y) : "l"(v)); return r;
}

// ====================== f32x2 SGEMM (128x128x16) ===========================
// C[M,N]=A[M,K]*B[K,N] row-major. 256 thr, 8 rows x 4 col-pairs per thread.
// Pipeline: regs=LDG(t); sync; STS(t); sync; LDG(t+1); compute(t).
__global__ __launch_bounds__(256, 2) void sgemm2(
    const float* __restrict__ A, const float* __restrict__ B,
    float* __restrict__ C, int M, int N, int K)
{
    __shared__ __align__(16) float As[16][132];   // stride 132: 16B-aligned rows
    __shared__ __align__(16) float Bs[16][128];

    const int tid = threadIdx.x;
    const int tx = tid & 15, ty = tid >> 4;
    const int m0 = blockIdx.y * 128, n0 = blockIdx.x * 128;

    // loader mapping: A row = tid&127 (conflict-free STS), k-half = tid>>7
    const int ar = tid & 127, akc = (tid >> 7) << 3;
    const int br = tid >> 5,  bnc = (tid & 31) << 2;
    const float* Agp = A + (size_t)(m0 + ar) * K + akc;
    const float* Bgp = B + (size_t)br * N + n0 + bnc;

    u64 acc[8][4];
#pragma unroll
    for (int r = 0; r < 8; r++)
#pragma unroll
        for (int c = 0; c < 4; c++) acc[r][c] = pack2(0.f, 0.f);

    float4 pa0, pa1, pb0, pb1;
    const int T = K >> 4;

    // prefetch tile 0
    pa0 = *(const float4*)(Agp);
    pa1 = *(const float4*)(Agp + 4);
    pb0 = *(const float4*)(Bgp);
    pb1 = *(const float4*)(Bgp + (size_t)8 * N);

    for (int t = 0; t < T; t++) {
        __syncthreads();   // compute(t-1) done with smem
        // STS tile t
        {
            const float av[8] = {pa0.x, pa0.y, pa0.z, pa0.w, pa1.x, pa1.y, pa1.z, pa1.w};
#pragma unroll
            for (int e = 0; e < 8; e++) As[akc + e][ar] = av[e];
            *(float4*)&Bs[br][bnc]     = pb0;
            *(float4*)&Bs[br + 8][bnc] = pb1;
        }
        __syncthreads();   // tile t visible

        // prefetch tile t+1 (consumed only after next sync)
        if (t + 1 < T) {
            const int k0 = (t + 1) << 4;
            pa0 = *(const float4*)(Agp + k0);
            pa1 = *(const float4*)(Agp + k0 + 4);
            pb0 = *(const float4*)(Bgp + (size_t)k0 * N);
            pb1 = *(const float4*)(Bgp + (size_t)(k0 + 8) * N);
        }

        // compute tile t
#pragma unroll
        for (int kk = 0; kk < 16; kk++) {
            float4 a0 = *(const float4*)&As[kk][ty * 8];
            float4 a1 = *(const float4*)&As[kk][ty * 8 + 4];
            float4 b0 = *(const float4*)&Bs[kk][tx * 8];
            float4 b1 = *(const float4*)&Bs[kk][tx * 8 + 4];
            u64 bp[4] = {pack2(b0.x, b0.y), pack2(b0.z, b0.w),
                         pack2(b1.x, b1.y), pack2(b1.z, b1.w)};
            const float av[8] = {a0.x, a0.y, a0.z, a0.w, a1.x, a1.y, a1.z, a1.w};
#pragma unroll
            for (int r = 0; r < 8; r++) {
                u64 ap = pack2(av[r], av[r]);
#pragma unroll
                for (int c = 0; c < 4; c++) fma2(acc[r][c], ap, bp[c]);
            }
        }
    }

#pragma unroll
    for (int r = 0; r < 8; r++) {
        float* crow = C + (size_t)(m0 + ty * 8 + r) * N + n0 + tx * 8;
        float2 v0 = unpack2(acc[r][0]), v1 = unpack2(acc[r][1]);
        float2 v2 = unpack2(acc[r][2]), v3 = unpack2(acc[r][3]);
        *(float4*)(crow)     = make_float4(v0.x, v0.y, v1.x, v1.y);
        *(float4*)(crow + 4) = make_float4(v2.x, v2.y, v3.x, v3.y);
    }
}

// ============================ RoPE tables ==================================
__global__ void rope_tables_kernel()
{
    int idx = blockIdx.x * blockDim.x + threadIdx.x;
    if (idx >= S_LEN * 32) return;
    int s = idx >> 5, j = idx & 31;
    double inv = exp(-((double)j / 32.0) * log(160000.0));
    double ang = (double)s * inv;
    g_cos[idx] = (float)cos(ang);
    g_sin[idx] = (float)sin(ang);
}

// ======================= RoPE apply (in-place on qkv) ======================
__global__ __launch_bounds__(256) void rope_apply_kernel()
{
    int idx = blockIdx.x * blockDim.x + threadIdx.x;
    if (idx >= ROWS * 1024) return;
    int row  = idx >> 10;
    int rem  = idx & 1023;
    int t    = rem >> 9;
    int rem2 = rem & 511;
    int h    = rem2 >> 5;
    int j    = rem2 & 31;
    int s    = row & (S_LEN - 1);

    size_t base = (size_t)row * 3072 + (size_t)t * HID + h * HD;
    float x1 = g_qkv[base + j];
    float x2 = g_qkv[base + j + 32];
    float c  = g_cos[s * 32 + j];
    float sn = g_sin[s * 32 + j];
    g_qkv[base + j]      = x1 * c - x2 * sn;
    g_qkv[base + j + 32] = x2 * c + x1 * sn;
}

// ================= fused causal flash attention (f32x2) ====================
// 64x64 tiles, 256 thr = 16x16 grid; thread owns 4 q-rows x 4 cols.
// smem: Qt[d][i] 64x64, Kt[d][j] 64x64, V[j][c] 64x68,
//       Pt 64x64 XOR-swizzled: word = j*64 + (col ^ (4*((j>>2)&7))).
#define OFF_QT 0
#define OFF_KT 4096
#define OFF_V  8192
#define OFF_PT 12544
#define ATTN_SMEM_F 16640   // floats (66560 B)

#define PTSWZ(j, col) ((j) * 64 + ((col) ^ (((j) >> 2 & 7) << 2)))

__global__ __launch_bounds__(256, 2) void attn2_kernel(
    const float* __restrict__ qkv, float* __restrict__ out)
{
    extern __shared__ __align__(16) float sm[];
    float* Qt = sm + OFF_QT;
    float* Kt = sm + OFF_KT;
    float* Vs = sm + OFF_V;
    float* Pt = sm + OFF_PT;

    const int tid = threadIdx.x;
    const int tx = tid & 15, ty = tid >> 4;
    const int i0 = ty * 4, c0 = tx * 4;          // q-rows; S j-cols / PV c-cols
    const int qt = blockIdx.x, bh = blockIdx.y;
    const int b = bh >> 4, h = bh & 15;
    const int q0 = qt * 64;
    const size_t rowbase = (size_t)b * S_LEN;
    const int qoff = h * HD, koff = HID + h * HD, voff = 2 * HID + h * HD;

    const int fr = tid & 63, fg = tid >> 6;       // fill: row, 16-col group

    // load Q transposed: Qt[d][i]
    {
        const float* qp = qkv + (rowbase + q0 + fr) * 3072 + qoff + fg * 16;
#pragma unroll
        for (int q = 0; q < 4; q++) {
            float4 v = *(const float4*)(qp + 4 * q);
            int d = fg * 16 + 4 * q;
            Qt[(d + 0) * 64 + fr] = v.x; Qt[(d + 1) * 64 + fr] = v.y;
            Qt[(d + 2) * 64 + fr] = v.z; Qt[(d + 3) * 64 + fr] = v.w;
        }
    }

    float mreg[4], lreg[4];
    u64 O[4][2];
#pragma unroll
    for (int r = 0; r < 4; r++) {
        mreg[r] = -INFINITY; lreg[r] = 0.f;
        O[r][0] = pack2(0.f, 0.f); O[r][1] = pack2(0.f, 0.f);
    }

    for (int j0 = 0; j0 <= q0; j0 += 64) {
        __syncthreads();   // prev PV done with Vs/Pt (and Q fill done, 1st iter)
        // load K transposed + V row-major
        {
            const float* kp = qkv + (rowbase + j0 + fr) * 3072 + koff + fg * 16;
#pragma unroll
            for (int q = 0; q < 4; q++) {
                float4 v = *(const float4*)(kp + 4 * q);
                int d = fg * 16 + 4 * q;
                Kt[(d + 0) * 64 + fr] = v.x; Kt[(d + 1) * 64 + fr] = v.y;
                Kt[(d + 2) * 64 + fr] = v.z; Kt[(d + 3) * 64 + fr] = v.w;
            }
            const float* vp = qkv + (rowbase + j0 + fr) * 3072 + voff + fg * 16;
#pragma unroll
            for (int q = 0; q < 4; q++)
                *(float4*)&Vs[fr * 68 + fg * 16 + 4 * q] = *(const float4*)(vp + 4 * q);
        }
        __syncthreads();   // Kt/Vs ready

        // ---- S = Q K^T : 4 rows x 2 col-pairs ----
        u64 sac[4][2];
#pragma unroll
        for (int r = 0; r < 4; r++) { sac[r][0] = pack2(0.f, 0.f); sac[r][1] = pack2(0.f, 0.f); }
#pragma unroll 4
        for (int d = 0; d < 64; d++) {
            float4 qv = *(const float4*)&Qt[d * 64 + i0];
            float4 kv = *(const float4*)&Kt[d * 64 + c0];
            u64 kp0 = pack2(kv.x, kv.y), kp1 = pack2(kv.z, kv.w);
            const float qa[4] = {qv.x, qv.y, qv.z, qv.w};
#pragma unroll
            for (int r = 0; r < 4; r++) {
                u64 qp = pack2(qa[r], qa[r]);
                fma2(sac[r][0], qp, kp0);
                fma2(sac[r][1], qp, kp1);
            }
        }

        // ---- softmax update (m/l in regs, width-16 shfl reductions) ----
        const bool diag = (j0 == q0);
        float ps[4][4], alpha[4];
#pragma unroll
        for (int r = 0; r < 4; r++) {
            float2 v0 = unpack2(sac[r][0]), v1 = unpack2(sac[r][1]);
            float sv[4] = {v0.x * 0.125f, v0.y * 0.125f, v1.x * 0.125f, v1.y * 0.125f};
            if (diag) {
#pragma unroll
                for (int cc = 0; cc < 4; cc++)
                    if (c0 + cc > i0 + r) sv[cc] = -1e9f;
            }
            float ml = fmaxf(fmaxf(sv[0], sv[1]), fmaxf(sv[2], sv[3]));
            ml = fmaxf(ml, __shfl_xor_sync(0xffffffffu, ml, 1));
            ml = fmaxf(ml, __shfl_xor_sync(0xffffffffu, ml, 2));
            ml = fmaxf(ml, __shfl_xor_sync(0xffffffffu, ml, 4));
            ml = fmaxf(ml, __shfl_xor_sync(0xffffffffu, ml, 8));
            float mn = fmaxf(mreg[r], ml);
            float a = __expf(mreg[r] - mn);
            mreg[r] = mn; alpha[r] = a;
            float rs = 0.f;
#pragma unroll
            for (int cc = 0; cc < 4; cc++) { ps[r][cc] = __expf(sv[cc] - mn); rs += ps[r][cc]; }
            rs += __shfl_xor_sync(0xffffffffu, rs, 1);
            rs += __shfl_xor_sync(0xffffffffu, rs, 2);
            rs += __shfl_xor_sync(0xffffffffu, rs, 4);
            rs += __shfl_xor_sync(0xffffffffu, rs, 8);
            lreg[r] = lreg[r] * a + rs;
        }
        // write P transposed (XOR-swizzled rows -> conflict-free STS.128)
#pragma unroll
        for (int cc = 0; cc < 4; cc++)
            *(float4*)&Pt[PTSWZ(c0 + cc, i0)] =
                make_float4(ps[0][cc], ps[1][cc], ps[2][cc], ps[3][cc]);
        // rescale O
#pragma unroll
        for (int r = 0; r < 4; r++) {
            u64 a2 = pack2(alpha[r], alpha[r]);
            O[r][0] = mul2(O[r][0], a2);
            O[r][1] = mul2(O[r][1], a2);
        }
        __syncthreads();   // Pt ready

        // ---- O += P V : 4 rows x 2 col-pairs ----
#pragma unroll 4
        for (int j = 0; j < 64; j++) {
            float4 pv = *(const float4*)&Pt[PTSWZ(j, i0)];
            float4 vv = *(const float4*)&Vs[j * 68 + c0];
            u64 vp0 = pack2(vv.x, vv.y), vp1 = pack2(vv.z, vv.w);
            const float pa[4] = {pv.x, pv.y, pv.z, pv.w};
#pragma unroll
            for (int r = 0; r < 4; r++) {
                u64 pp = pack2(pa[r], pa[r]);
                fma2(O[r][0], pp, vp0);
                fma2(O[r][1], pp, vp1);
            }
        }
    }

#pragma unroll
    for (int r = 0; r < 4; r++) {
        float linv = 1.0f / lreg[r];
        float2 v0 = unpack2(O[r][0]), v1 = unpack2(O[r][1]);
        *(float4*)(out + (rowbase + q0 + i0 + r) * HID + h * HD + c0) =
            make_float4(v0.x * linv, v0.y * linv, v1.x * linv, v1.y * linv);
    }
}

// ================================ launch ===================================
extern "C" void kernel_launch(void* const* d_in, const int* in_sizes, int n_in,
                              void* d_out, int out_size)
{
    const float* hidden = (const float*)d_in[0];
    const float* Wqkv = (const float*)d_in[2];
    const float* Wo   = (const float*)d_in[3];
    float* out = (float*)d_out;

    float *qkv_ptr, *att_ptr;
    cudaGetSymbolAddress((void**)&qkv_ptr, g_qkv);
    cudaGetSymbolAddress((void**)&att_ptr, g_att);

    rope_tables_kernel<<<(S_LEN * 32 + 255) / 256, 256>>>();

    sgemm2<<<dim3(3 * HID / 128, ROWS / 128), 256>>>(hidden, Wqkv, qkv_ptr, ROWS, 3 * HID, HID);

    rope_apply_kernel<<<(ROWS * 1024) / 256, 256>>>();

    const int SMEM = ATTN_SMEM_F * 4;
    cudaFuncSetAttribute(attn2_kernel, cudaFuncAttributeMaxDynamicSharedMemorySize, SMEM);
    dim3 g2(S_LEN / 64, BATCH * NH);
    attn2_kernel<<<g2, 256, SMEM>>>(qkv_ptr, att_ptr);

    sgemm2<<<dim3(HID / 128, ROWS / 128), 256>>>(att_ptr, Wo, out, ROWS, HID, HID);
}